// round 10
// baseline (speedup 1.0000x reference)
#include <cuda_runtime.h>
#include <cuda_fp16.h>
#include <math.h>
#include <stdint.h>

#define BATCH 256
#define MEAS  32
#define TBEAT 512
#define INDIM 512
#define HDIM  1024
#define ODIM  128
#define G4    4096
#define KBEAT 1152

#define BM    128
#define BNC   64
#define AP    72            // A stage pitch (halfs): 144B rows, ldmatrix conflict-free
#define PBK   64            // persistent-kernel K tile

// ---------------- scratch ----------------------------------------------------
__device__ __half g_WbH[G4 * KBEAT];    // beat weights, K order [inputs | h]
__device__ __half g_mWihH[G4 * INDIM];
__device__ __half g_mWhhH[G4 * HDIM];
__device__ __half g_latWH[G4 * HDIM];
__device__ __half g_linWH[ODIM * HDIM];
__device__ __half g_latentH[BATCH * MEAS * INDIM];
__device__ __half g_inH[BATCH * TBEAT * ODIM];
__device__ float  g_xg[BATCH * MEAS * G4];
__device__ __half g_lat[BATCH * MEAS * HDIM];
__device__ float  g_latproj[BATCH * MEAS * G4];
__device__ __half g_h0[BATCH * HDIM];
__device__ __half g_h1[BATCH * HDIM];
__device__ __half g_hall[BATCH * TBEAT * HDIM];
__device__ unsigned g_barG[64];         // [0] and [32]: per-row-group barriers

__device__ __forceinline__ float sigf(float x) { return 1.0f / (1.0f + expf(-x)); }

__device__ __forceinline__ uint32_t s2u(const void* p) {
    uint32_t a;
    asm("{ .reg .u64 t; cvta.to.shared.u64 t, %1; cvt.u32.u64 %0, t; }"
        : "=r"(a) : "l"(p));
    return a;
}

__device__ __forceinline__ void mma_f16(float* c, const uint32_t* a, const uint32_t* b) {
    asm volatile(
        "mma.sync.aligned.m16n8k16.row.col.f32.f16.f16.f32 "
        "{%0,%1,%2,%3}, {%4,%5,%6,%7}, {%8,%9}, {%0,%1,%2,%3};"
        : "+f"(c[0]), "+f"(c[1]), "+f"(c[2]), "+f"(c[3])
        : "r"(a[0]), "r"(a[1]), "r"(a[2]), "r"(a[3]), "r"(b[0]), "r"(b[1]));
}

__device__ __forceinline__ void ldsm4(uint32_t& r0, uint32_t& r1, uint32_t& r2,
                                      uint32_t& r3, uint32_t saddr) {
    asm volatile("ldmatrix.sync.aligned.m8n8.x4.shared.b16 {%0,%1,%2,%3}, [%4];"
                 : "=r"(r0), "=r"(r1), "=r"(r2), "=r"(r3) : "r"(saddr));
}

__device__ __forceinline__ void cpa16(uint32_t sa, const void* g) {
    asm volatile("cp.async.cg.shared.global [%0], [%1], 16;" :: "r"(sa), "l"(g));
}
#define CPA_COMMIT() asm volatile("cp.async.commit_group;")
#define CPA_WAIT(n)  asm volatile("cp.async.wait_group %0;" :: "n"(n))

// ---------------- fused prep kernel ------------------------------------------
__global__ void prep_all_k(const float* __restrict__ latent,
                           const float* __restrict__ inputs,
                           const float* __restrict__ mWih,
                           const float* __restrict__ mWhh,
                           const float* __restrict__ bWih,
                           const float* __restrict__ bWhh,
                           const float* __restrict__ linW) {
    const int n = blockIdx.x;
    const int tid = threadIdx.x;
    for (int k = tid; k < INDIM; k += 256)
        g_mWihH[(size_t)n * INDIM + k] = __float2half(mWih[(size_t)n * INDIM + k]);
    for (int k = tid; k < HDIM; k += 256) {
        g_mWhhH[(size_t)n * HDIM + k] = __float2half(mWhh[(size_t)n * HDIM + k]);
        g_latWH[(size_t)n * HDIM + k] = __float2half(bWih[(size_t)n * KBEAT + k]);
    }
    // beat weights, K order [inputs(128) | h(1024)]
    for (int k = tid; k < KBEAT; k += 256) {
        float v = (k < ODIM) ? bWih[(size_t)n * KBEAT + HDIM + k]
                             : bWhh[(size_t)n * HDIM + (k - ODIM)];
        g_WbH[(size_t)n * KBEAT + k] = __float2half(v);
    }
    if (n < ODIM)
        for (int k = tid; k < HDIM; k += 256)
            g_linWH[(size_t)n * HDIM + k] = __float2half(linW[(size_t)n * HDIM + k]);
    {
        const size_t base = (size_t)n * 1024;
        for (int i = tid; i < 1024; i += 256)
            g_latentH[base + i] = __float2half(latent[base + i]);
    }
    {
        const size_t base = (size_t)n * 4096;
        for (int i = tid; i < 4096; i += 256)
            g_inH[base + i] = __float2half(inputs[base + i]);
    }
    if (tid < 64) g_h0[n * 64 + tid] = __float2half(0.f);
    if (n == 0 && tid < 64) g_barG[tid] = 0u;
}

__global__ void zero_h_k() {
    int i = blockIdx.x * blockDim.x + threadIdx.x;
    if (i < BATCH * HDIM) g_h0[i] = __float2half(0.f);
    if (i < 64) g_barG[i] = 0u;
}

// ---------------- persistent fused LSTM recurrence ---------------------------
// Grid 64x2 = 128 CTAs. W tile SMEM-resident; A streamed (4 slots, 3 in flight).
// Warp-specialized compute: warps 0-3 (one per SMSP) each own an m64 x n32 tile
// (A frags reused 4x, B frags 4x -> SMEM crossbar below tensor pipe); all 8
// warps issue cp.async loads. c-state in registers; split 64-CTA barrier.
template<int KDIM, bool HAS_EXTRA, int NSTEPS>
__global__ void __launch_bounds__(256, 1) lstm_persist_k(
    const __half* __restrict__ extra,
    const __half* __restrict__ W,
    const float* __restrict__ add_base,
    __half* __restrict__ hb0, __half* __restrict__ hb1,
    __half* __restrict__ tanh_out, long long tanh_rstride)
{
    constexpr int WP = KDIM + 8;
    constexpr int nk = KDIM / PBK;
    extern __shared__ __half sm[];
    const uint32_t asmb = s2u(sm);                       // 4 * BM * AP halfs
    const uint32_t wsmb = asmb + 4 * BM * AP * 2;        // resident W

    const int tid  = threadIdx.x;
    const int wid  = tid >> 5;
    const int lane = tid & 31;
    const int wm   = (wid >> 1) & 1;    // compute warps 0-3: row group (64 rows)
    const int wn   = wid & 1;           // col group (8 units)
    const int q    = lane & 3;
    const int rg   = lane >> 2;
    const int nblk = blockIdx.x;
    const int mblk = blockIdx.y * BM;
    unsigned* barp = &g_barG[blockIdx.y * 32];

    // ---- one-time: resident W tile load (gate-major smem rows) ----
    for (int idx = tid; idx < 64 * (KDIM / 8); idx += 256) {
        int sr = idx / (KDIM / 8);
        int k8 = (idx % (KDIM / 8)) * 8;
        int brow = ((sr >> 3) & 3) * HDIM + nblk * 16 + ((sr >> 5) << 3) + (sr & 7);
        cpa16(wsmb + (uint32_t)(sr * WP + k8) * 2, W + (size_t)brow * KDIM + k8);
    }
    CPA_COMMIT();
    CPA_WAIT(0);
    __syncthreads();

    // ---- A loader mapping: 4 chunks of 16B per thread per tile (all warps) ----
    const int rA = tid >> 3;
    const int k8a = (tid & 7) << 3;
    uint32_t adst[4];
#pragma unroll
    for (int p = 0; p < 4; p++) adst[p] = (uint32_t)((rA + 32 * p) * AP + k8a) * 2;
    const __half* exr[4];
#pragma unroll
    for (int p = 0; p < 4; p++)
        exr[p] = HAS_EXTRA ?
            (extra + (size_t)(mblk + rA + 32 * p) * (TBEAT * ODIM) + k8a)
            : (const __half*)0;

    // ---- ldmatrix offsets (compute warps) ----
    const uint32_t aoff = (uint32_t)((wm * 64 + (lane & 15)) * AP + ((lane >> 4) << 3)) * 2;
    const uint32_t bbase = wsmb +
        (uint32_t)((wn * 32 + (lane & 7) + ((lane >> 4) << 3)) * WP + (((lane >> 3) & 1) << 3)) * 2;

    float creg[16];
#pragma unroll
    for (int i = 0; i < 16; i++) creg[i] = 0.f;
    unsigned barTarget = 0;

#pragma unroll 1
    for (int t = 0; t < NSTEPS; ++t) {
        const __half* hin = (t & 1) ? hb1 : hb0;
        __half* hout = (t & 1) ? hb0 : hb1;
        const int tOD = t * ODIM;

        auto issue = [&](int it) {
            const int kt = it * PBK;
            const uint32_t sb = asmb + (uint32_t)(it & 3) * (BM * AP * 2);
#pragma unroll
            for (int p = 0; p < 4; p++) {
                const __half* src = (HAS_EXTRA && kt < ODIM)
                    ? (exr[p] + tOD + kt)
                    : (hin + (size_t)(mblk + rA + 32 * p) * HDIM + k8a
                       + (HAS_EXTRA ? (kt - ODIM) : kt));
                cpa16(sb + adst[p], src);
            }
            CPA_COMMIT();
        };

        // ---- pre-barrier: barrier-independent input chunks ----
        if (HAS_EXTRA) { issue(0); issue(1); }

        // ---- split-group barrier wait (h(t-1) visibility) ----
        if (t > 0) {
            if (tid == 0) {
                unsigned v;
                do {
                    asm volatile("ld.acquire.gpu.global.u32 %0, [%1];"
                                 : "=r"(v) : "l"(barp));
                } while (v < barTarget);
            }
            __syncthreads();
        }

        // ---- post-barrier: h chunks; keep 3 groups in flight ----
        if (HAS_EXTRA) { issue(2); }
        else           { issue(0); issue(1); issue(2); }

        float acc[4][4][4];
#pragma unroll
        for (int a = 0; a < 4; a++)
#pragma unroll
            for (int b = 0; b < 4; b++)
#pragma unroll
                for (int cc = 0; cc < 4; cc++) acc[a][b][cc] = 0.f;

#pragma unroll 1
        for (int it = 0; it < nk; ++it) {
            CPA_WAIT(2);
            __syncthreads();
            if (wid < 4) {
                const uint32_t ab = asmb + (uint32_t)(it & 3) * (BM * AP * 2);
                const uint32_t kgb = (uint32_t)(it * PBK) * 2;

                uint32_t af[2][4][4], bf[2][4][2];
                auto ldfrag = [&](int buf, int ko) {
#pragma unroll
                    for (int mt = 0; mt < 4; mt++)
                        ldsm4(af[buf][mt][0], af[buf][mt][1], af[buf][mt][2], af[buf][mt][3],
                              ab + aoff + (uint32_t)(mt * 16 * AP + ko * 16) * 2);
#pragma unroll
                    for (int gp = 0; gp < 2; gp++)
                        ldsm4(bf[buf][gp * 2][0], bf[buf][gp * 2][1],
                              bf[buf][gp * 2 + 1][0], bf[buf][gp * 2 + 1][1],
                              bbase + (uint32_t)(gp * 16 * WP) * 2 + kgb + (uint32_t)(ko * 16) * 2);
                };

                ldfrag(0, 0);
#pragma unroll
                for (int ko = 0; ko < 4; ++ko) {
                    if (ko < 3) ldfrag((ko + 1) & 1, ko + 1);
                    const int cb = ko & 1;
#pragma unroll
                    for (int nt = 0; nt < 4; nt++)
#pragma unroll
                        for (int mt = 0; mt < 4; mt++)
                            mma_f16(acc[mt][nt], af[cb][mt], bf[cb][nt]);
                }
            }
            if (it + 3 < nk) issue(it + 3);
        }
        CPA_WAIT(0);

        // ---- fused LSTM epilogue (compute warps; adds loaded L2-hot) ----
        if (wid < 4) {
            const float* adp = add_base
                + (size_t)(HAS_EXTRA ? (t >> 4) : t) * G4;
            const int jb = nblk * 16 + wn * 8 + 2 * q;
#pragma unroll
            for (int mt = 0; mt < 4; mt++)
#pragma unroll
                for (int rs = 0; rs < 2; rs++) {
                    const int r = mblk + wm * 64 + mt * 16 + rg + rs * 8;
                    const float* ad = adp + (size_t)r * (MEAS * G4) + jb;
                    float2 a0 = *(const float2*)(ad);
                    float2 a1 = *(const float2*)(ad + HDIM);
                    float2 a2 = *(const float2*)(ad + 2 * HDIM);
                    float2 a3 = *(const float2*)(ad + 3 * HDIM);
                    __half2 hv, tv;
#pragma unroll
                    for (int ps = 0; ps < 2; ps++) {
                        const int ai = rs * 2 + ps;
                        float gi = acc[mt][0][ai] + (ps ? a0.y : a0.x);
                        float gf = acc[mt][1][ai] + (ps ? a1.y : a1.x);
                        float gg = acc[mt][2][ai] + (ps ? a2.y : a2.x);
                        float go = acc[mt][3][ai] + (ps ? a3.y : a3.x);
                        const int ci = mt * 4 + rs * 2 + ps;
                        float cc = sigf(gf) * creg[ci] + sigf(gi) * tanhf(gg);
                        creg[ci] = cc;
                        float hh = sigf(go) * tanhf(cc);
                        if (ps == 0) { hv.x = __float2half(hh); tv.x = __float2half(tanhf(hh)); }
                        else         { hv.y = __float2half(hh); tv.y = __float2half(tanhf(hh)); }
                    }
                    *(__half2*)(hout + (size_t)r * HDIM + jb) = hv;
                    *(__half2*)(tanh_out + (size_t)r * tanh_rstride
                                + (size_t)t * HDIM + jb) = tv;
                }
        }

        // ---- release arrive (wait happens at top of next step) ----
        if (t + 1 < NSTEPS) {
            __threadfence();
            __syncthreads();
            if (tid == 0) {
                unsigned x;
                asm volatile("atom.add.release.gpu.global.u32 %0, [%1], 1;"
                             : "=r"(x) : "l"(barp));
            }
            barTarget += 64;
        }
    }
}

// ---------------- fp16 tensor GEMM (non-recurrent projections) --------------
#define BK  32
#define GAP 40
#define GBP 40
#define GSTAGE_HALFS (BM * GAP + BNC * GBP)
#define GSMEM_BYTES  (4 * GSTAGE_HALFS * 2)

__global__ void __launch_bounds__(256, 2) gemm_k(
    const __half* __restrict__ A, int lda,
    const __half* __restrict__ W, int ldw, int K,
    const float* __restrict__ bias,
    float* __restrict__ C, int ldc)
{
    extern __shared__ __half sm[];
    const uint32_t smb = s2u(sm);
    const int tid  = threadIdx.x;
    const int wid  = tid >> 5;
    const int lane = tid & 31;
    const int wm   = wid >> 1;
    const int wn   = wid & 1;
    const int q    = lane & 3;
    const int rg   = lane >> 2;
    const int mblk = blockIdx.y * BM;
    const int nblk = blockIdx.x;

    const int rA0 = tid >> 2, rA1 = rA0 + 64;
    const int k8a = (tid & 3) << 3;
    const __half* Ap0 = A + (size_t)(mblk + rA0) * lda + k8a;
    const __half* Ap1 = A + (size_t)(mblk + rA1) * lda + k8a;
    const uint32_t adst0 = (uint32_t)(rA0 * GAP + k8a) * 2;
    const uint32_t adst1 = (uint32_t)(rA1 * GAP + k8a) * 2;
    const int sr  = tid >> 2;
    const int k8b = (tid & 3) << 3;
    const __half* Bp = W + (size_t)(nblk * BNC + sr) * ldw + k8b;
    const uint32_t bdst = (uint32_t)(BM * GAP + sr * GBP + k8b) * 2;

    const int nk = K / BK;
    auto issue = [&](int s, int it) {
        const int kt = it * BK;
        const uint32_t sb = smb + (uint32_t)s * (GSTAGE_HALFS * 2);
        cpa16(sb + adst0, Ap0 + kt);
        cpa16(sb + adst1, Ap1 + kt);
        cpa16(sb + bdst, Bp + kt);
    };
    issue(0, 0); CPA_COMMIT();
    issue(1, 1); CPA_COMMIT();
    issue(2, 2); CPA_COMMIT();

    const uint32_t aoff = (uint32_t)((wm * 32 + (lane & 15)) * GAP + ((lane >> 4) << 3)) * 2;
    const uint32_t boff = (uint32_t)(BM * GAP +
        (wn * 32 + (lane & 7) + ((lane >> 4) << 3)) * GBP + (((lane >> 3) & 1) << 3)) * 2;

    float acc[2][4][4];
#pragma unroll
    for (int a = 0; a < 2; a++)
#pragma unroll
        for (int b = 0; b < 4; b++)
#pragma unroll
            for (int cc = 0; cc < 4; cc++) acc[a][b][cc] = 0.f;

    int st = 0;
    for (int it = 0; it < nk; ++it) {
        CPA_WAIT(2);
        __syncthreads();
        const uint32_t sb = smb + (uint32_t)st * (GSTAGE_HALFS * 2);
#pragma unroll
        for (int ko = 0; ko < 2; ++ko) {
            uint32_t a[2][4];
#pragma unroll
            for (int mt = 0; mt < 2; mt++)
                ldsm4(a[mt][0], a[mt][1], a[mt][2], a[mt][3],
                      sb + aoff + (uint32_t)(mt * 16 * GAP + ko * 16) * 2);
            uint32_t bfr[4][2];
#pragma unroll
            for (int gp = 0; gp < 2; gp++)
                ldsm4(bfr[gp * 2][0], bfr[gp * 2][1],
                      bfr[gp * 2 + 1][0], bfr[gp * 2 + 1][1],
                      sb + boff + (uint32_t)(gp * 16 * GBP + ko * 16) * 2);
#pragma unroll
            for (int nt = 0; nt < 4; nt++)
#pragma unroll
                for (int mt = 0; mt < 2; mt++)
                    mma_f16(acc[mt][nt], a[mt], bfr[nt]);
        }
        if (it + 3 < nk) issue((it + 3) & 3, it + 3);
        CPA_COMMIT();
        st = (st + 1) & 3;
    }
    CPA_WAIT(0);

#pragma unroll
    for (int mt = 0; mt < 2; mt++)
#pragma unroll
        for (int nt = 0; nt < 4; nt++)
#pragma unroll
            for (int rs = 0; rs < 2; rs++) {
                const int r = mblk + wm * 32 + mt * 16 + rg + rs * 8;
                const int col = nblk * BNC + wn * 32 + nt * 8 + 2 * q;
                float2 o;
                o.x = acc[mt][nt][rs * 2 + 0] + bias[col];
                o.y = acc[mt][nt][rs * 2 + 1] + bias[col + 1];
                *(float2*)&C[(size_t)r * ldc + col] = o;
            }
}

// ---------------------------------------------------------------------------
extern "C" void kernel_launch(void* const* d_in, const int* in_sizes, int n_in,
                              void* d_out, int out_size) {
    const float* latent = (const float*)d_in[0];
    const float* inputs = (const float*)d_in[1];
    const float* mWih   = (const float*)d_in[2];
    const float* mWhh   = (const float*)d_in[3];
    const float* mb     = (const float*)d_in[4];
    const float* bWih   = (const float*)d_in[5];
    const float* bWhh   = (const float*)d_in[6];
    const float* bb     = (const float*)d_in[7];
    const float* linW   = (const float*)d_in[8];
    const float* linb   = (const float*)d_in[9];
    float* out = (float*)d_out;

    __half *p_WbH, *p_mWihH, *p_mWhhH, *p_latWH, *p_linWH, *p_latentH, *p_inH;
    __half *p_lat, *p_h0, *p_h1, *p_hall;
    float *p_xg, *p_latproj;
    cudaGetSymbolAddress((void**)&p_WbH, g_WbH);
    cudaGetSymbolAddress((void**)&p_mWihH, g_mWihH);
    cudaGetSymbolAddress((void**)&p_mWhhH, g_mWhhH);
    cudaGetSymbolAddress((void**)&p_latWH, g_latWH);
    cudaGetSymbolAddress((void**)&p_linWH, g_linWH);
    cudaGetSymbolAddress((void**)&p_latentH, g_latentH);
    cudaGetSymbolAddress((void**)&p_inH, g_inH);
    cudaGetSymbolAddress((void**)&p_xg, g_xg);
    cudaGetSymbolAddress((void**)&p_lat, g_lat);
    cudaGetSymbolAddress((void**)&p_latproj, g_latproj);
    cudaGetSymbolAddress((void**)&p_h0, g_h0);
    cudaGetSymbolAddress((void**)&p_h1, g_h1);
    cudaGetSymbolAddress((void**)&p_hall, g_hall);

    const int measSmem = (4 * BM * AP + 64 * (HDIM + 8)) * 2;    // 205,824
    const int beatSmem = (4 * BM * AP + 64 * (KBEAT + 8)) * 2;   // 222,208
    cudaFuncSetAttribute(lstm_persist_k<HDIM, false, MEAS>,
                         cudaFuncAttributeMaxDynamicSharedMemorySize, measSmem);
    cudaFuncSetAttribute(lstm_persist_k<KBEAT, true, TBEAT>,
                         cudaFuncAttributeMaxDynamicSharedMemorySize, beatSmem);
    cudaFuncSetAttribute(gemm_k, cudaFuncAttributeMaxDynamicSharedMemorySize,
                         GSMEM_BYTES);

    // launch 1: fused prep (also zeroes h0 + barriers)
    prep_all_k<<<G4, 256>>>(latent, inputs, mWih, mWhh, bWih, bWhh, linW);

    // launch 2: measure input projection xg = latent @ mWih^T + mb
    gemm_k<<<dim3(G4 / BNC, (BATCH * MEAS) / BM), 256, GSMEM_BYTES>>>(
        p_latentH, INDIM, p_mWihH, INDIM, INDIM, mb, p_xg, G4);

    // launch 3: measure LSTM, persistent, 32 steps
    lstm_persist_k<HDIM, false, MEAS><<<dim3(64, 2), 256, measSmem>>>(
        nullptr, p_mWhhH, p_xg, p_h0, p_h1, p_lat, (long long)MEAS * HDIM);

    // launch 4: beat latent projection latproj = lat @ bWih[:, :H]^T + bb
    gemm_k<<<dim3(G4 / BNC, (BATCH * MEAS) / BM), 256, GSMEM_BYTES>>>(
        p_lat, HDIM, p_latWH, HDIM, HDIM, bb, p_latproj, G4);

    // launch 5: re-zero h0 + barriers
    zero_h_k<<<(BATCH * HDIM) / 256, 256>>>();

    // launch 6: beat LSTM, persistent, 512 steps
    lstm_persist_k<KBEAT, true, TBEAT><<<dim3(64, 2), 256, beatSmem>>>(
        p_inH, p_WbH, p_latproj, p_h0, p_h1, p_hall, (long long)TBEAT * HDIM);

    // launch 7: output head out = tanh(h_all) @ linW^T + linb
    gemm_k<<<dim3(ODIM / BNC, (BATCH * TBEAT) / BM), 256, GSMEM_BYTES>>>(
        p_hall, HDIM, p_linWH, HDIM, HDIM, linb, out, ODIM);
}

// round 11
// speedup vs baseline: 1.1996x; 1.1996x over previous
#include <cuda_runtime.h>
#include <cuda_fp16.h>
#include <math.h>
#include <stdint.h>

#define BATCH 256
#define MEAS  32
#define TBEAT 512
#define INDIM 512
#define HDIM  1024
#define ODIM  128
#define G4    4096
#define KBEAT 1152

#define BM    128
#define BNC   64
#define AP    72            // A stage pitch (halfs): 144B rows, ldmatrix conflict-free
#define PBK   64            // persistent-kernel K tile
#define PTHREADS 384        // 8 compute warps + 4 loader warps

// ---------------- scratch ----------------------------------------------------
__device__ __half g_WbH[G4 * KBEAT];    // beat weights, K order [inputs | h]
__device__ __half g_mWihH[G4 * INDIM];
__device__ __half g_mWhhH[G4 * HDIM];
__device__ __half g_latWH[G4 * HDIM];
__device__ __half g_linWH[ODIM * HDIM];
__device__ __half g_latentH[BATCH * MEAS * INDIM];
__device__ __half g_inH[BATCH * TBEAT * ODIM];
__device__ float  g_xg[BATCH * MEAS * G4];
__device__ __half g_lat[BATCH * MEAS * HDIM];
__device__ float  g_latproj[BATCH * MEAS * G4];
__device__ __half g_h0[BATCH * HDIM];
__device__ __half g_h1[BATCH * HDIM];
__device__ __half g_hall[BATCH * TBEAT * HDIM];
__device__ unsigned g_barG[64];         // [0] and [32]: per-row-group barriers

__device__ __forceinline__ float sigf(float x) { return 1.0f / (1.0f + expf(-x)); }

__device__ __forceinline__ uint32_t s2u(const void* p) {
    uint32_t a;
    asm("{ .reg .u64 t; cvta.to.shared.u64 t, %1; cvt.u32.u64 %0, t; }"
        : "=r"(a) : "l"(p));
    return a;
}

__device__ __forceinline__ void mma_f16(float* c, const uint32_t* a, const uint32_t* b) {
    asm volatile(
        "mma.sync.aligned.m16n8k16.row.col.f32.f16.f16.f32 "
        "{%0,%1,%2,%3}, {%4,%5,%6,%7}, {%8,%9}, {%0,%1,%2,%3};"
        : "+f"(c[0]), "+f"(c[1]), "+f"(c[2]), "+f"(c[3])
        : "r"(a[0]), "r"(a[1]), "r"(a[2]), "r"(a[3]), "r"(b[0]), "r"(b[1]));
}

__device__ __forceinline__ void ldsm4(uint32_t& r0, uint32_t& r1, uint32_t& r2,
                                      uint32_t& r3, uint32_t saddr) {
    asm volatile("ldmatrix.sync.aligned.m8n8.x4.shared.b16 {%0,%1,%2,%3}, [%4];"
                 : "=r"(r0), "=r"(r1), "=r"(r2), "=r"(r3) : "r"(saddr));
}

__device__ __forceinline__ void cpa16(uint32_t sa, const void* g) {
    asm volatile("cp.async.cg.shared.global [%0], [%1], 16;" :: "r"(sa), "l"(g));
}
#define CPA_COMMIT() asm volatile("cp.async.commit_group;")
#define CPA_WAIT(n)  asm volatile("cp.async.wait_group %0;" :: "n"(n))

// ---------------- fused prep kernel ------------------------------------------
__global__ void prep_all_k(const float* __restrict__ latent,
                           const float* __restrict__ inputs,
                           const float* __restrict__ mWih,
                           const float* __restrict__ mWhh,
                           const float* __restrict__ bWih,
                           const float* __restrict__ bWhh,
                           const float* __restrict__ linW) {
    const int n = blockIdx.x;
    const int tid = threadIdx.x;
    for (int k = tid; k < INDIM; k += 256)
        g_mWihH[(size_t)n * INDIM + k] = __float2half(mWih[(size_t)n * INDIM + k]);
    for (int k = tid; k < HDIM; k += 256) {
        g_mWhhH[(size_t)n * HDIM + k] = __float2half(mWhh[(size_t)n * HDIM + k]);
        g_latWH[(size_t)n * HDIM + k] = __float2half(bWih[(size_t)n * KBEAT + k]);
    }
    // beat weights, K order [inputs(128) | h(1024)]
    for (int k = tid; k < KBEAT; k += 256) {
        float v = (k < ODIM) ? bWih[(size_t)n * KBEAT + HDIM + k]
                             : bWhh[(size_t)n * HDIM + (k - ODIM)];
        g_WbH[(size_t)n * KBEAT + k] = __float2half(v);
    }
    if (n < ODIM)
        for (int k = tid; k < HDIM; k += 256)
            g_linWH[(size_t)n * HDIM + k] = __float2half(linW[(size_t)n * HDIM + k]);
    {
        const size_t base = (size_t)n * 1024;
        for (int i = tid; i < 1024; i += 256)
            g_latentH[base + i] = __float2half(latent[base + i]);
    }
    {
        const size_t base = (size_t)n * 4096;
        for (int i = tid; i < 4096; i += 256)
            g_inH[base + i] = __float2half(inputs[base + i]);
    }
    if (tid < 64) g_h0[n * 64 + tid] = __float2half(0.f);
    if (n == 0 && tid < 64) g_barG[tid] = 0u;
}

__global__ void zero_h_k() {
    int i = blockIdx.x * blockDim.x + threadIdx.x;
    if (i < BATCH * HDIM) g_h0[i] = __float2half(0.f);
    if (i < 64) g_barG[i] = 0u;
}

// ---------------- persistent fused LSTM recurrence ---------------------------
// Grid 64x2 = 128 CTAs, 384 threads. W tile SMEM-resident; A streamed (4 slots,
// 3 in flight) by 4 DEDICATED loader warps (8-11); warps 0-7 compute m32 x n32
// tiles with fragment double-buffering; c-state + adds in registers; split
// 64-CTA release/acquire barrier between steps.
template<int KDIM, bool HAS_EXTRA, int NSTEPS>
__global__ void __launch_bounds__(PTHREADS, 1) lstm_persist_k(
    const __half* __restrict__ extra,
    const __half* __restrict__ W,
    const float* __restrict__ add_base,
    __half* __restrict__ hb0, __half* __restrict__ hb1,
    __half* __restrict__ tanh_out, long long tanh_rstride)
{
    constexpr int WP = KDIM + 8;
    constexpr int nk = KDIM / PBK;
    extern __shared__ __half sm[];
    const uint32_t asmb = s2u(sm);                       // 4 * BM * AP halfs
    const uint32_t wsmb = asmb + 4 * BM * AP * 2;        // resident W

    const int tid  = threadIdx.x;
    const int wid  = tid >> 5;
    const int lane = tid & 31;
    const bool isLoader = (wid >= 8);
    const int wm   = (wid >> 1) & 3;    // compute warps: 32-row group
    const int wn   = wid & 1;           // compute warps: 8-unit group
    const int q    = lane & 3;
    const int rg   = lane >> 2;
    const int nblk = blockIdx.x;
    const int mblk = blockIdx.y * BM;
    unsigned* barp = &g_barG[blockIdx.y * 32];

    // ---- one-time: resident W tile load (gate-major smem rows) ----
    for (int idx = tid; idx < 64 * (KDIM / 8); idx += PTHREADS) {
        int sr = idx / (KDIM / 8);
        int k8 = (idx % (KDIM / 8)) * 8;
        int brow = ((sr >> 3) & 3) * HDIM + nblk * 16 + ((sr >> 5) << 3) + (sr & 7);
        cpa16(wsmb + (uint32_t)(sr * WP + k8) * 2, W + (size_t)brow * KDIM + k8);
    }
    CPA_COMMIT();
    CPA_WAIT(0);
    __syncthreads();

    // ---- loader mapping (warps 8-11): 8 chunks of 16B per thread per tile ----
    const int lt  = isLoader ? (tid - 256) : 0;   // 0..127
    const int rL  = lt >> 3;                       // 0..15
    const int k8L = (lt & 7) << 3;                 // 0..56
    uint32_t adst[8];
    const __half* exr[8];
#pragma unroll
    for (int i = 0; i < 8; i++) {
        adst[i] = (uint32_t)((rL + 16 * i) * AP + k8L) * 2;
        exr[i] = HAS_EXTRA ?
            (extra + (size_t)(mblk + rL + 16 * i) * (TBEAT * ODIM) + k8L)
            : (const __half*)0;
    }

    // ---- ldmatrix offsets (compute warps) ----
    const uint32_t aoff = (uint32_t)((wm * 32 + (lane & 15)) * AP + ((lane >> 4) << 3)) * 2;
    const uint32_t bbase = wsmb +
        (uint32_t)((wn * 32 + (lane & 7) + ((lane >> 4) << 3)) * WP + (((lane >> 3) & 1) << 3)) * 2;

    float creg[8];
#pragma unroll
    for (int i = 0; i < 8; i++) creg[i] = 0.f;
    unsigned barTarget = 0;

#pragma unroll 1
    for (int t = 0; t < NSTEPS; ++t) {
        const __half* hin = (t & 1) ? hb1 : hb0;
        __half* hout = (t & 1) ? hb0 : hb1;
        const int tOD = t * ODIM;

        auto issue = [&](int it) {       // loader threads only
            const int kt = it * PBK;
            const uint32_t sb = asmb + (uint32_t)(it & 3) * (BM * AP * 2);
#pragma unroll
            for (int i = 0; i < 8; i++) {
                const __half* src = (HAS_EXTRA && kt < ODIM)
                    ? (exr[i] + tOD + kt)
                    : (hin + (size_t)(mblk + rL + 16 * i) * HDIM + k8L
                       + (HAS_EXTRA ? (kt - ODIM) : kt));
                cpa16(sb + adst[i], src);
            }
            CPA_COMMIT();
        };

        // ---- pre-barrier: loaders issue barrier-independent input chunks;
        //      compute warps prefetch adds (L2-hot latproj/xg) ----
        if (isLoader) {
            if (HAS_EXTRA) { issue(0); issue(1); }
        }
        float2 ads[2][2][4];
        if (!isLoader) {
            const float* adp = add_base
                + (size_t)(HAS_EXTRA ? (t >> 4) : t) * G4;
            const int jb = nblk * 16 + wn * 8 + 2 * q;
#pragma unroll
            for (int mt = 0; mt < 2; mt++)
#pragma unroll
                for (int rs = 0; rs < 2; rs++) {
                    const int r = mblk + wm * 32 + mt * 16 + rg + rs * 8;
                    const float* ad = adp + (size_t)r * (MEAS * G4) + jb;
#pragma unroll
                    for (int gg = 0; gg < 4; gg++)
                        ads[mt][rs][gg] = *(const float2*)(ad + gg * HDIM);
                }
        }

        // ---- split-group barrier wait (h(t-1) visibility) ----
        if (t > 0) {
            if (tid == 0) {
                unsigned v;
                do {
                    asm volatile("ld.acquire.gpu.global.u32 %0, [%1];"
                                 : "=r"(v) : "l"(barp));
                } while (v < barTarget);
            }
            __syncthreads();
        }

        // ---- post-barrier: loaders issue h chunks; 3 groups in flight ----
        if (isLoader) {
            if (HAS_EXTRA) { issue(2); }
            else           { issue(0); issue(1); issue(2); }
        }

        float acc[2][4][4];
#pragma unroll
        for (int a = 0; a < 2; a++)
#pragma unroll
            for (int b = 0; b < 4; b++)
#pragma unroll
                for (int cc = 0; cc < 4; cc++) acc[a][b][cc] = 0.f;

#pragma unroll 1
        for (int it = 0; it < nk; ++it) {
            CPA_WAIT(2);                 // loaders: throttle; compute: no-op
            __syncthreads();
            if (!isLoader) {
                const uint32_t ab = asmb + (uint32_t)(it & 3) * (BM * AP * 2);
                const uint32_t kgb = (uint32_t)(it * PBK) * 2;

                uint32_t af[2][2][4], bf[2][4][2];
                auto ldfrag = [&](int buf, int ko) {
#pragma unroll
                    for (int mt = 0; mt < 2; mt++)
                        ldsm4(af[buf][mt][0], af[buf][mt][1], af[buf][mt][2], af[buf][mt][3],
                              ab + aoff + (uint32_t)(mt * 16 * AP + ko * 16) * 2);
#pragma unroll
                    for (int gp = 0; gp < 2; gp++)
                        ldsm4(bf[buf][gp * 2][0], bf[buf][gp * 2][1],
                              bf[buf][gp * 2 + 1][0], bf[buf][gp * 2 + 1][1],
                              bbase + (uint32_t)(gp * 16 * WP) * 2 + kgb + (uint32_t)(ko * 16) * 2);
                };

                ldfrag(0, 0);
#pragma unroll
                for (int ko = 0; ko < 4; ++ko) {
                    if (ko < 3) ldfrag((ko + 1) & 1, ko + 1);
                    const int cb = ko & 1;
#pragma unroll
                    for (int nt = 0; nt < 4; nt++)
#pragma unroll
                        for (int mt = 0; mt < 2; mt++)
                            mma_f16(acc[mt][nt], af[cb][mt], bf[cb][nt]);
                }
            } else {
                if (it + 3 < nk) issue(it + 3);
            }
        }
        CPA_WAIT(0);

        // ---- fused LSTM epilogue (compute warps; c and adds in registers) ----
        if (!isLoader) {
#pragma unroll
            for (int mt = 0; mt < 2; mt++)
#pragma unroll
                for (int rs = 0; rs < 2; rs++)
#pragma unroll
                    for (int ps = 0; ps < 2; ps++) {
                        const int r = mblk + wm * 32 + mt * 16 + rg + rs * 8;
                        const int j = nblk * 16 + wn * 8 + 2 * q + ps;
                        const int ai = rs * 2 + ps;
                        float gi = acc[mt][0][ai] + (ps ? ads[mt][rs][0].y : ads[mt][rs][0].x);
                        float gf = acc[mt][1][ai] + (ps ? ads[mt][rs][1].y : ads[mt][rs][1].x);
                        float gg = acc[mt][2][ai] + (ps ? ads[mt][rs][2].y : ads[mt][rs][2].x);
                        float go = acc[mt][3][ai] + (ps ? ads[mt][rs][3].y : ads[mt][rs][3].x);
                        const int ci = mt * 4 + rs * 2 + ps;
                        float cc = sigf(gf) * creg[ci] + sigf(gi) * tanhf(gg);
                        creg[ci] = cc;
                        float hh = sigf(go) * tanhf(cc);
                        hout[r * HDIM + j] = __float2half(hh);
                        tanh_out[(size_t)r * tanh_rstride + (size_t)t * HDIM + j] =
                            __float2half(tanhf(hh));
                    }
        }

        // ---- release arrive (wait happens at top of next step) ----
        if (t + 1 < NSTEPS) {
            __threadfence();
            __syncthreads();
            if (tid == 0) {
                unsigned x;
                asm volatile("atom.add.release.gpu.global.u32 %0, [%1], 1;"
                             : "=r"(x) : "l"(barp));
            }
            barTarget += 64;
        }
    }
}

// ---------------- fp16 tensor GEMM (non-recurrent projections) --------------
#define BK  32
#define GAP 40
#define GBP 40
#define GSTAGE_HALFS (BM * GAP + BNC * GBP)
#define GSMEM_BYTES  (4 * GSTAGE_HALFS * 2)

__global__ void __launch_bounds__(256, 2) gemm_k(
    const __half* __restrict__ A, int lda,
    const __half* __restrict__ W, int ldw, int K,
    const float* __restrict__ bias,
    float* __restrict__ C, int ldc)
{
    extern __shared__ __half sm[];
    const uint32_t smb = s2u(sm);
    const int tid  = threadIdx.x;
    const int wid  = tid >> 5;
    const int lane = tid & 31;
    const int wm   = wid >> 1;
    const int wn   = wid & 1;
    const int q    = lane & 3;
    const int rg   = lane >> 2;
    const int mblk = blockIdx.y * BM;
    const int nblk = blockIdx.x;

    const int rA0 = tid >> 2, rA1 = rA0 + 64;
    const int k8a = (tid & 3) << 3;
    const __half* Ap0 = A + (size_t)(mblk + rA0) * lda + k8a;
    const __half* Ap1 = A + (size_t)(mblk + rA1) * lda + k8a;
    const uint32_t adst0 = (uint32_t)(rA0 * GAP + k8a) * 2;
    const uint32_t adst1 = (uint32_t)(rA1 * GAP + k8a) * 2;
    const int sr  = tid >> 2;
    const int k8b = (tid & 3) << 3;
    const __half* Bp = W + (size_t)(nblk * BNC + sr) * ldw + k8b;
    const uint32_t bdst = (uint32_t)(BM * GAP + sr * GBP + k8b) * 2;

    const int nk = K / BK;
    auto issue = [&](int s, int it) {
        const int kt = it * BK;
        const uint32_t sb = smb + (uint32_t)s * (GSTAGE_HALFS * 2);
        cpa16(sb + adst0, Ap0 + kt);
        cpa16(sb + adst1, Ap1 + kt);
        cpa16(sb + bdst, Bp + kt);
    };
    issue(0, 0); CPA_COMMIT();
    issue(1, 1); CPA_COMMIT();
    issue(2, 2); CPA_COMMIT();

    const uint32_t aoff = (uint32_t)((wm * 32 + (lane & 15)) * GAP + ((lane >> 4) << 3)) * 2;
    const uint32_t boff = (uint32_t)(BM * GAP +
        (wn * 32 + (lane & 7) + ((lane >> 4) << 3)) * GBP + (((lane >> 3) & 1) << 3)) * 2;

    float acc[2][4][4];
#pragma unroll
    for (int a = 0; a < 2; a++)
#pragma unroll
        for (int b = 0; b < 4; b++)
#pragma unroll
            for (int cc = 0; cc < 4; cc++) acc[a][b][cc] = 0.f;

    int st = 0;
    for (int it = 0; it < nk; ++it) {
        CPA_WAIT(2);
        __syncthreads();
        const uint32_t sb = smb + (uint32_t)st * (GSTAGE_HALFS * 2);
#pragma unroll
        for (int ko = 0; ko < 2; ++ko) {
            uint32_t a[2][4];
#pragma unroll
            for (int mt = 0; mt < 2; mt++)
                ldsm4(a[mt][0], a[mt][1], a[mt][2], a[mt][3],
                      sb + aoff + (uint32_t)(mt * 16 * GAP + ko * 16) * 2);
            uint32_t bfr[4][2];
#pragma unroll
            for (int gp = 0; gp < 2; gp++)
                ldsm4(bfr[gp * 2][0], bfr[gp * 2][1],
                      bfr[gp * 2 + 1][0], bfr[gp * 2 + 1][1],
                      sb + boff + (uint32_t)(gp * 16 * GBP + ko * 16) * 2);
#pragma unroll
            for (int nt = 0; nt < 4; nt++)
#pragma unroll
                for (int mt = 0; mt < 2; mt++)
                    mma_f16(acc[mt][nt], a[mt], bfr[nt]);
        }
        if (it + 3 < nk) issue((it + 3) & 3, it + 3);
        CPA_COMMIT();
        st = (st + 1) & 3;
    }
    CPA_WAIT(0);

#pragma unroll
    for (int mt = 0; mt < 2; mt++)
#pragma unroll
        for (int nt = 0; nt < 4; nt++)
#pragma unroll
            for (int rs = 0; rs < 2; rs++) {
                const int r = mblk + wm * 32 + mt * 16 + rg + rs * 8;
                const int col = nblk * BNC + wn * 32 + nt * 8 + 2 * q;
                float2 o;
                o.x = acc[mt][nt][rs * 2 + 0] + bias[col];
                o.y = acc[mt][nt][rs * 2 + 1] + bias[col + 1];
                *(float2*)&C[(size_t)r * ldc + col] = o;
            }
}

// ---------------------------------------------------------------------------
extern "C" void kernel_launch(void* const* d_in, const int* in_sizes, int n_in,
                              void* d_out, int out_size) {
    const float* latent = (const float*)d_in[0];
    const float* inputs = (const float*)d_in[1];
    const float* mWih   = (const float*)d_in[2];
    const float* mWhh   = (const float*)d_in[3];
    const float* mb     = (const float*)d_in[4];
    const float* bWih   = (const float*)d_in[5];
    const float* bWhh   = (const float*)d_in[6];
    const float* bb     = (const float*)d_in[7];
    const float* linW   = (const float*)d_in[8];
    const float* linb   = (const float*)d_in[9];
    float* out = (float*)d_out;

    __half *p_WbH, *p_mWihH, *p_mWhhH, *p_latWH, *p_linWH, *p_latentH, *p_inH;
    __half *p_lat, *p_h0, *p_h1, *p_hall;
    float *p_xg, *p_latproj;
    cudaGetSymbolAddress((void**)&p_WbH, g_WbH);
    cudaGetSymbolAddress((void**)&p_mWihH, g_mWihH);
    cudaGetSymbolAddress((void**)&p_mWhhH, g_mWhhH);
    cudaGetSymbolAddress((void**)&p_latWH, g_latWH);
    cudaGetSymbolAddress((void**)&p_linWH, g_linWH);
    cudaGetSymbolAddress((void**)&p_latentH, g_latentH);
    cudaGetSymbolAddress((void**)&p_inH, g_inH);
    cudaGetSymbolAddress((void**)&p_xg, g_xg);
    cudaGetSymbolAddress((void**)&p_lat, g_lat);
    cudaGetSymbolAddress((void**)&p_latproj, g_latproj);
    cudaGetSymbolAddress((void**)&p_h0, g_h0);
    cudaGetSymbolAddress((void**)&p_h1, g_h1);
    cudaGetSymbolAddress((void**)&p_hall, g_hall);

    const int measSmem = (4 * BM * AP + 64 * (HDIM + 8)) * 2;    // 205,824
    const int beatSmem = (4 * BM * AP + 64 * (KBEAT + 8)) * 2;   // 222,208
    cudaFuncSetAttribute(lstm_persist_k<HDIM, false, MEAS>,
                         cudaFuncAttributeMaxDynamicSharedMemorySize, measSmem);
    cudaFuncSetAttribute(lstm_persist_k<KBEAT, true, TBEAT>,
                         cudaFuncAttributeMaxDynamicSharedMemorySize, beatSmem);
    cudaFuncSetAttribute(gemm_k, cudaFuncAttributeMaxDynamicSharedMemorySize,
                         GSMEM_BYTES);

    // launch 1: fused prep (also zeroes h0 + barriers)
    prep_all_k<<<G4, 256>>>(latent, inputs, mWih, mWhh, bWih, bWhh, linW);

    // launch 2: measure input projection xg = latent @ mWih^T + mb
    gemm_k<<<dim3(G4 / BNC, (BATCH * MEAS) / BM), 256, GSMEM_BYTES>>>(
        p_latentH, INDIM, p_mWihH, INDIM, INDIM, mb, p_xg, G4);

    // launch 3: measure LSTM, persistent, 32 steps
    lstm_persist_k<HDIM, false, MEAS><<<dim3(64, 2), PTHREADS, measSmem>>>(
        nullptr, p_mWhhH, p_xg, p_h0, p_h1, p_lat, (long long)MEAS * HDIM);

    // launch 4: beat latent projection latproj = lat @ bWih[:, :H]^T + bb
    gemm_k<<<dim3(G4 / BNC, (BATCH * MEAS) / BM), 256, GSMEM_BYTES>>>(
        p_lat, HDIM, p_latWH, HDIM, HDIM, bb, p_latproj, G4);

    // launch 5: re-zero h0 + barriers
    zero_h_k<<<(BATCH * HDIM) / 256, 256>>>();

    // launch 6: beat LSTM, persistent, 512 steps
    lstm_persist_k<KBEAT, true, TBEAT><<<dim3(64, 2), PTHREADS, beatSmem>>>(
        p_inH, p_WbH, p_latproj, p_h0, p_h1, p_hall, (long long)TBEAT * HDIM);

    // launch 7: output head out = tanh(h_all) @ linW^T + linb
    gemm_k<<<dim3(ODIM / BNC, (BATCH * TBEAT) / BM), 256, GSMEM_BYTES>>>(
        p_hall, HDIM, p_linWH, HDIM, HDIM, linb, out, ODIM);
}

// round 12
// speedup vs baseline: 1.3011x; 1.0847x over previous
#include <cuda_runtime.h>
#include <cuda_fp16.h>
#include <math.h>
#include <stdint.h>

#define BATCH 256
#define MEAS  32
#define TBEAT 512
#define INDIM 512
#define HDIM  1024
#define ODIM  128
#define G4    4096
#define KBEAT 1152

#define BM    128
#define BNC   64
#define AP    72            // A stage pitch (halfs): 144B rows, ldmatrix conflict-free
#define PBK   64            // persistent-kernel K tile
#define PTHREADS 384        // 8 compute warps + 4 loader warps

// ---------------- scratch ----------------------------------------------------
__device__ __half g_WbH[G4 * KBEAT];    // beat weights, K order [inputs | h]
__device__ __half g_mWihH[G4 * INDIM];
__device__ __half g_mWhhH[G4 * HDIM];
__device__ __half g_latWH[G4 * HDIM];
__device__ __half g_linWH[ODIM * HDIM];
__device__ __half g_latentH[BATCH * MEAS * INDIM];
__device__ __half g_inH[BATCH * TBEAT * ODIM];
__device__ float  g_xg[BATCH * MEAS * G4];
__device__ __half g_lat[BATCH * MEAS * HDIM];
__device__ float  g_latproj[BATCH * MEAS * G4];
__device__ __half g_h0[BATCH * HDIM];
__device__ __half g_h1[BATCH * HDIM];
__device__ __half g_hall[BATCH * TBEAT * HDIM];
__device__ unsigned g_barG[64];         // [0] and [32]: per-row-group barriers

// MUFU tanh; sigmoid via tanh identity (abs err ~2^-11, same order as fp16 rounding)
__device__ __forceinline__ float tanh_fast(float x) {
    float r;
    asm("tanh.approx.f32 %0, %1;" : "=f"(r) : "f"(x));
    return r;
}
__device__ __forceinline__ float sig_fast(float x) {
    return fmaf(tanh_fast(0.5f * x), 0.5f, 0.5f);
}

__device__ __forceinline__ uint32_t s2u(const void* p) {
    uint32_t a;
    asm("{ .reg .u64 t; cvta.to.shared.u64 t, %1; cvt.u32.u64 %0, t; }"
        : "=r"(a) : "l"(p));
    return a;
}

__device__ __forceinline__ void mma_f16(float* c, const uint32_t* a, const uint32_t* b) {
    asm volatile(
        "mma.sync.aligned.m16n8k16.row.col.f32.f16.f16.f32 "
        "{%0,%1,%2,%3}, {%4,%5,%6,%7}, {%8,%9}, {%0,%1,%2,%3};"
        : "+f"(c[0]), "+f"(c[1]), "+f"(c[2]), "+f"(c[3])
        : "r"(a[0]), "r"(a[1]), "r"(a[2]), "r"(a[3]), "r"(b[0]), "r"(b[1]));
}

__device__ __forceinline__ void ldsm4(uint32_t& r0, uint32_t& r1, uint32_t& r2,
                                      uint32_t& r3, uint32_t saddr) {
    asm volatile("ldmatrix.sync.aligned.m8n8.x4.shared.b16 {%0,%1,%2,%3}, [%4];"
                 : "=r"(r0), "=r"(r1), "=r"(r2), "=r"(r3) : "r"(saddr));
}

__device__ __forceinline__ void cpa16(uint32_t sa, const void* g) {
    asm volatile("cp.async.cg.shared.global [%0], [%1], 16;" :: "r"(sa), "l"(g));
}
#define CPA_COMMIT() asm volatile("cp.async.commit_group;")
#define CPA_WAIT(n)  asm volatile("cp.async.wait_group %0;" :: "n"(n))

// ---------------- fused prep kernel ------------------------------------------
__global__ void prep_all_k(const float* __restrict__ latent,
                           const float* __restrict__ inputs,
                           const float* __restrict__ mWih,
                           const float* __restrict__ mWhh,
                           const float* __restrict__ bWih,
                           const float* __restrict__ bWhh,
                           const float* __restrict__ linW) {
    const int n = blockIdx.x;
    const int tid = threadIdx.x;
    for (int k = tid; k < INDIM; k += 256)
        g_mWihH[(size_t)n * INDIM + k] = __float2half(mWih[(size_t)n * INDIM + k]);
    for (int k = tid; k < HDIM; k += 256) {
        g_mWhhH[(size_t)n * HDIM + k] = __float2half(mWhh[(size_t)n * HDIM + k]);
        g_latWH[(size_t)n * HDIM + k] = __float2half(bWih[(size_t)n * KBEAT + k]);
    }
    // beat weights, K order [inputs(128) | h(1024)]
    for (int k = tid; k < KBEAT; k += 256) {
        float v = (k < ODIM) ? bWih[(size_t)n * KBEAT + HDIM + k]
                             : bWhh[(size_t)n * HDIM + (k - ODIM)];
        g_WbH[(size_t)n * KBEAT + k] = __float2half(v);
    }
    if (n < ODIM)
        for (int k = tid; k < HDIM; k += 256)
            g_linWH[(size_t)n * HDIM + k] = __float2half(linW[(size_t)n * HDIM + k]);
    {
        const size_t base = (size_t)n * 1024;
        for (int i = tid; i < 1024; i += 256)
            g_latentH[base + i] = __float2half(latent[base + i]);
    }
    {
        const size_t base = (size_t)n * 4096;
        for (int i = tid; i < 4096; i += 256)
            g_inH[base + i] = __float2half(inputs[base + i]);
    }
    if (tid < 64) g_h0[n * 64 + tid] = __float2half(0.f);
    if (n == 0 && tid < 64) g_barG[tid] = 0u;
}

__global__ void zero_h_k() {
    int i = blockIdx.x * blockDim.x + threadIdx.x;
    if (i < BATCH * HDIM) g_h0[i] = __float2half(0.f);
    if (i < 64) g_barG[i] = 0u;
}

// ---------------- persistent fused LSTM recurrence ---------------------------
// Grid 64x2 = 128 CTAs, 384 threads. W tile SMEM-resident; A streamed (4 slots,
// 3 in flight) by 4 DEDICATED loader warps (8-11); warps 0-7 compute m32 x n32
// tiles with fragment double-buffering; c-state + adds in registers; split
// 64-CTA release/acquire barrier between steps; MUFU fast activations.
template<int KDIM, bool HAS_EXTRA, int NSTEPS>
__global__ void __launch_bounds__(PTHREADS, 1) lstm_persist_k(
    const __half* __restrict__ extra,
    const __half* __restrict__ W,
    const float* __restrict__ add_base,
    __half* __restrict__ hb0, __half* __restrict__ hb1,
    __half* __restrict__ tanh_out, long long tanh_rstride)
{
    constexpr int WP = KDIM + 8;
    constexpr int nk = KDIM / PBK;
    extern __shared__ __half sm[];
    const uint32_t asmb = s2u(sm);                       // 4 * BM * AP halfs
    const uint32_t wsmb = asmb + 4 * BM * AP * 2;        // resident W

    const int tid  = threadIdx.x;
    const int wid  = tid >> 5;
    const int lane = tid & 31;
    const bool isLoader = (wid >= 8);
    const int wm   = (wid >> 1) & 3;    // compute warps: 32-row group
    const int wn   = wid & 1;           // compute warps: 8-unit group
    const int q    = lane & 3;
    const int rg   = lane >> 2;
    const int nblk = blockIdx.x;
    const int mblk = blockIdx.y * BM;
    unsigned* barp = &g_barG[blockIdx.y * 32];

    // ---- one-time: resident W tile load (gate-major smem rows) ----
    for (int idx = tid; idx < 64 * (KDIM / 8); idx += PTHREADS) {
        int sr = idx / (KDIM / 8);
        int k8 = (idx % (KDIM / 8)) * 8;
        int brow = ((sr >> 3) & 3) * HDIM + nblk * 16 + ((sr >> 5) << 3) + (sr & 7);
        cpa16(wsmb + (uint32_t)(sr * WP + k8) * 2, W + (size_t)brow * KDIM + k8);
    }
    CPA_COMMIT();
    CPA_WAIT(0);
    __syncthreads();

    // ---- loader mapping (warps 8-11): 8 chunks of 16B per thread per tile ----
    const int lt  = isLoader ? (tid - 256) : 0;   // 0..127
    const int rL  = lt >> 3;                       // 0..15
    const int k8L = (lt & 7) << 3;                 // 0..56
    uint32_t adst[8];
    const __half* exr[8];
#pragma unroll
    for (int i = 0; i < 8; i++) {
        adst[i] = (uint32_t)((rL + 16 * i) * AP + k8L) * 2;
        exr[i] = HAS_EXTRA ?
            (extra + (size_t)(mblk + rL + 16 * i) * (TBEAT * ODIM) + k8L)
            : (const __half*)0;
    }

    // ---- ldmatrix offsets (compute warps) ----
    const uint32_t aoff = (uint32_t)((wm * 32 + (lane & 15)) * AP + ((lane >> 4) << 3)) * 2;
    const uint32_t bbase = wsmb +
        (uint32_t)((wn * 32 + (lane & 7) + ((lane >> 4) << 3)) * WP + (((lane >> 3) & 1) << 3)) * 2;

    float creg[8];
#pragma unroll
    for (int i = 0; i < 8; i++) creg[i] = 0.f;
    unsigned barTarget = 0;

#pragma unroll 1
    for (int t = 0; t < NSTEPS; ++t) {
        const __half* hin = (t & 1) ? hb1 : hb0;
        __half* hout = (t & 1) ? hb0 : hb1;
        const int tOD = t * ODIM;

        auto issue = [&](int it) {       // loader threads only
            const int kt = it * PBK;
            const uint32_t sb = asmb + (uint32_t)(it & 3) * (BM * AP * 2);
#pragma unroll
            for (int i = 0; i < 8; i++) {
                const __half* src = (HAS_EXTRA && kt < ODIM)
                    ? (exr[i] + tOD + kt)
                    : (hin + (size_t)(mblk + rL + 16 * i) * HDIM + k8L
                       + (HAS_EXTRA ? (kt - ODIM) : kt));
                cpa16(sb + adst[i], src);
            }
            CPA_COMMIT();
        };

        // ---- pre-barrier: loaders issue barrier-independent input chunks;
        //      compute warps prefetch adds (L2-hot latproj/xg) ----
        if (isLoader) {
            if (HAS_EXTRA) { issue(0); issue(1); }
        }
        float2 ads[2][2][4];
        if (!isLoader) {
            const float* adp = add_base
                + (size_t)(HAS_EXTRA ? (t >> 4) : t) * G4;
            const int jb = nblk * 16 + wn * 8 + 2 * q;
#pragma unroll
            for (int mt = 0; mt < 2; mt++)
#pragma unroll
                for (int rs = 0; rs < 2; rs++) {
                    const int r = mblk + wm * 32 + mt * 16 + rg + rs * 8;
                    const float* ad = adp + (size_t)r * (MEAS * G4) + jb;
#pragma unroll
                    for (int gg = 0; gg < 4; gg++)
                        ads[mt][rs][gg] = *(const float2*)(ad + gg * HDIM);
                }
        }

        // ---- split-group barrier wait (h(t-1) visibility) ----
        if (t > 0) {
            if (tid == 0) {
                unsigned v;
                do {
                    asm volatile("ld.acquire.gpu.global.u32 %0, [%1];"
                                 : "=r"(v) : "l"(barp));
                } while (v < barTarget);
            }
            __syncthreads();
        }

        // ---- post-barrier: loaders issue h chunks; 3 groups in flight ----
        if (isLoader) {
            if (HAS_EXTRA) { issue(2); }
            else           { issue(0); issue(1); issue(2); }
        }

        float acc[2][4][4];
#pragma unroll
        for (int a = 0; a < 2; a++)
#pragma unroll
            for (int b = 0; b < 4; b++)
#pragma unroll
                for (int cc = 0; cc < 4; cc++) acc[a][b][cc] = 0.f;

#pragma unroll 1
        for (int it = 0; it < nk; ++it) {
            CPA_WAIT(2);                 // loaders: throttle; compute: no-op
            __syncthreads();
            if (!isLoader) {
                const uint32_t ab = asmb + (uint32_t)(it & 3) * (BM * AP * 2);
                const uint32_t kgb = (uint32_t)(it * PBK) * 2;

                uint32_t af[2][2][4], bf[2][4][2];
                auto ldfrag = [&](int buf, int ko) {
#pragma unroll
                    for (int mt = 0; mt < 2; mt++)
                        ldsm4(af[buf][mt][0], af[buf][mt][1], af[buf][mt][2], af[buf][mt][3],
                              ab + aoff + (uint32_t)(mt * 16 * AP + ko * 16) * 2);
#pragma unroll
                    for (int gp = 0; gp < 2; gp++)
                        ldsm4(bf[buf][gp * 2][0], bf[buf][gp * 2][1],
                              bf[buf][gp * 2 + 1][0], bf[buf][gp * 2 + 1][1],
                              bbase + (uint32_t)(gp * 16 * WP) * 2 + kgb + (uint32_t)(ko * 16) * 2);
                };

                ldfrag(0, 0);
#pragma unroll
                for (int ko = 0; ko < 4; ++ko) {
                    if (ko < 3) ldfrag((ko + 1) & 1, ko + 1);
                    const int cb = ko & 1;
#pragma unroll
                    for (int nt = 0; nt < 4; nt++)
#pragma unroll
                        for (int mt = 0; mt < 2; mt++)
                            mma_f16(acc[mt][nt], af[cb][mt], bf[cb][nt]);
                }
            } else {
                if (it + 3 < nk) issue(it + 3);
            }
        }
        CPA_WAIT(0);

        // ---- fused LSTM epilogue (MUFU activations; c + adds in registers) ----
        if (!isLoader) {
#pragma unroll
            for (int mt = 0; mt < 2; mt++)
#pragma unroll
                for (int rs = 0; rs < 2; rs++)
#pragma unroll
                    for (int ps = 0; ps < 2; ps++) {
                        const int r = mblk + wm * 32 + mt * 16 + rg + rs * 8;
                        const int j = nblk * 16 + wn * 8 + 2 * q + ps;
                        const int ai = rs * 2 + ps;
                        float gi = acc[mt][0][ai] + (ps ? ads[mt][rs][0].y : ads[mt][rs][0].x);
                        float gf = acc[mt][1][ai] + (ps ? ads[mt][rs][1].y : ads[mt][rs][1].x);
                        float gg = acc[mt][2][ai] + (ps ? ads[mt][rs][2].y : ads[mt][rs][2].x);
                        float go = acc[mt][3][ai] + (ps ? ads[mt][rs][3].y : ads[mt][rs][3].x);
                        const int ci = mt * 4 + rs * 2 + ps;
                        float cc = sig_fast(gf) * creg[ci] + sig_fast(gi) * tanh_fast(gg);
                        creg[ci] = cc;
                        float hh = sig_fast(go) * tanh_fast(cc);
                        hout[r * HDIM + j] = __float2half(hh);
                        tanh_out[(size_t)r * tanh_rstride + (size_t)t * HDIM + j] =
                            __float2half(tanh_fast(hh));
                    }
        }

        // ---- release arrive (release-atomic after CTA barrier; no MEMBAR) ----
        if (t + 1 < NSTEPS) {
            __syncthreads();
            if (tid == 0) {
                unsigned x;
                asm volatile("atom.add.release.gpu.global.u32 %0, [%1], 1;"
                             : "=r"(x) : "l"(barp));
            }
            barTarget += 64;
        }
    }
}

// ---------------- fp16 tensor GEMM (non-recurrent projections) --------------
#define BK  32
#define GAP 40
#define GBP 40
#define GSTAGE_HALFS (BM * GAP + BNC * GBP)
#define GSMEM_BYTES  (4 * GSTAGE_HALFS * 2)

__global__ void __launch_bounds__(256, 2) gemm_k(
    const __half* __restrict__ A, int lda,
    const __half* __restrict__ W, int ldw, int K,
    const float* __restrict__ bias,
    float* __restrict__ C, int ldc)
{
    extern __shared__ __half sm[];
    const uint32_t smb = s2u(sm);
    const int tid  = threadIdx.x;
    const int wid  = tid >> 5;
    const int lane = tid & 31;
    const int wm   = wid >> 1;
    const int wn   = wid & 1;
    const int q    = lane & 3;
    const int rg   = lane >> 2;
    const int mblk = blockIdx.y * BM;
    const int nblk = blockIdx.x;

    const int rA0 = tid >> 2, rA1 = rA0 + 64;
    const int k8a = (tid & 3) << 3;
    const __half* Ap0 = A + (size_t)(mblk + rA0) * lda + k8a;
    const __half* Ap1 = A + (size_t)(mblk + rA1) * lda + k8a;
    const uint32_t adst0 = (uint32_t)(rA0 * GAP + k8a) * 2;
    const uint32_t adst1 = (uint32_t)(rA1 * GAP + k8a) * 2;
    const int sr  = tid >> 2;
    const int k8b = (tid & 3) << 3;
    const __half* Bp = W + (size_t)(nblk * BNC + sr) * ldw + k8b;
    const uint32_t bdst = (uint32_t)(BM * GAP + sr * GBP + k8b) * 2;

    const int nk = K / BK;
    auto issue = [&](int s, int it) {
        const int kt = it * BK;
        const uint32_t sb = smb + (uint32_t)s * (GSTAGE_HALFS * 2);
        cpa16(sb + adst0, Ap0 + kt);
        cpa16(sb + adst1, Ap1 + kt);
        cpa16(sb + bdst, Bp + kt);
    };
    issue(0, 0); CPA_COMMIT();
    issue(1, 1); CPA_COMMIT();
    issue(2, 2); CPA_COMMIT();

    const uint32_t aoff = (uint32_t)((wm * 32 + (lane & 15)) * GAP + ((lane >> 4) << 3)) * 2;
    const uint32_t boff = (uint32_t)(BM * GAP +
        (wn * 32 + (lane & 7) + ((lane >> 4) << 3)) * GBP + (((lane >> 3) & 1) << 3)) * 2;

    float acc[2][4][4];
#pragma unroll
    for (int a = 0; a < 2; a++)
#pragma unroll
        for (int b = 0; b < 4; b++)
#pragma unroll
            for (int cc = 0; cc < 4; cc++) acc[a][b][cc] = 0.f;

    int st = 0;
    for (int it = 0; it < nk; ++it) {
        CPA_WAIT(2);
        __syncthreads();
        const uint32_t sb = smb + (uint32_t)st * (GSTAGE_HALFS * 2);
#pragma unroll
        for (int ko = 0; ko < 2; ++ko) {
            uint32_t a[2][4];
#pragma unroll
            for (int mt = 0; mt < 2; mt++)
                ldsm4(a[mt][0], a[mt][1], a[mt][2], a[mt][3],
                      sb + aoff + (uint32_t)(mt * 16 * GAP + ko * 16) * 2);
            uint32_t bfr[4][2];
#pragma unroll
            for (int gp = 0; gp < 2; gp++)
                ldsm4(bfr[gp * 2][0], bfr[gp * 2][1],
                      bfr[gp * 2 + 1][0], bfr[gp * 2 + 1][1],
                      sb + boff + (uint32_t)(gp * 16 * GBP + ko * 16) * 2);
#pragma unroll
            for (int nt = 0; nt < 4; nt++)
#pragma unroll
                for (int mt = 0; mt < 2; mt++)
                    mma_f16(acc[mt][nt], a[mt], bfr[nt]);
        }
        if (it + 3 < nk) issue((it + 3) & 3, it + 3);
        CPA_COMMIT();
        st = (st + 1) & 3;
    }
    CPA_WAIT(0);

#pragma unroll
    for (int mt = 0; mt < 2; mt++)
#pragma unroll
        for (int nt = 0; nt < 4; nt++)
#pragma unroll
            for (int rs = 0; rs < 2; rs++) {
                const int r = mblk + wm * 32 + mt * 16 + rg + rs * 8;
                const int col = nblk * BNC + wn * 32 + nt * 8 + 2 * q;
                float2 o;
                o.x = acc[mt][nt][rs * 2 + 0] + bias[col];
                o.y = acc[mt][nt][rs * 2 + 1] + bias[col + 1];
                *(float2*)&C[(size_t)r * ldc + col] = o;
            }
}

// ---------------------------------------------------------------------------
extern "C" void kernel_launch(void* const* d_in, const int* in_sizes, int n_in,
                              void* d_out, int out_size) {
    const float* latent = (const float*)d_in[0];
    const float* inputs = (const float*)d_in[1];
    const float* mWih   = (const float*)d_in[2];
    const float* mWhh   = (const float*)d_in[3];
    const float* mb     = (const float*)d_in[4];
    const float* bWih   = (const float*)d_in[5];
    const float* bWhh   = (const float*)d_in[6];
    const float* bb     = (const float*)d_in[7];
    const float* linW   = (const float*)d_in[8];
    const float* linb   = (const float*)d_in[9];
    float* out = (float*)d_out;

    __half *p_WbH, *p_mWihH, *p_mWhhH, *p_latWH, *p_linWH, *p_latentH, *p_inH;
    __half *p_lat, *p_h0, *p_h1, *p_hall;
    float *p_xg, *p_latproj;
    cudaGetSymbolAddress((void**)&p_WbH, g_WbH);
    cudaGetSymbolAddress((void**)&p_mWihH, g_mWihH);
    cudaGetSymbolAddress((void**)&p_mWhhH, g_mWhhH);
    cudaGetSymbolAddress((void**)&p_latWH, g_latWH);
    cudaGetSymbolAddress((void**)&p_linWH, g_linWH);
    cudaGetSymbolAddress((void**)&p_latentH, g_latentH);
    cudaGetSymbolAddress((void**)&p_inH, g_inH);
    cudaGetSymbolAddress((void**)&p_xg, g_xg);
    cudaGetSymbolAddress((void**)&p_lat, g_lat);
    cudaGetSymbolAddress((void**)&p_latproj, g_latproj);
    cudaGetSymbolAddress((void**)&p_h0, g_h0);
    cudaGetSymbolAddress((void**)&p_h1, g_h1);
    cudaGetSymbolAddress((void**)&p_hall, g_hall);

    const int measSmem = (4 * BM * AP + 64 * (HDIM + 8)) * 2;    // 205,824
    const int beatSmem = (4 * BM * AP + 64 * (KBEAT + 8)) * 2;   // 222,208
    cudaFuncSetAttribute(lstm_persist_k<HDIM, false, MEAS>,
                         cudaFuncAttributeMaxDynamicSharedMemorySize, measSmem);
    cudaFuncSetAttribute(lstm_persist_k<KBEAT, true, TBEAT>,
                         cudaFuncAttributeMaxDynamicSharedMemorySize, beatSmem);
    cudaFuncSetAttribute(gemm_k, cudaFuncAttributeMaxDynamicSharedMemorySize,
                         GSMEM_BYTES);

    // launch 1: fused prep (also zeroes h0 + barriers)
    prep_all_k<<<G4, 256>>>(latent, inputs, mWih, mWhh, bWih, bWhh, linW);

    // launch 2: measure input projection xg = latent @ mWih^T + mb
    gemm_k<<<dim3(G4 / BNC, (BATCH * MEAS) / BM), 256, GSMEM_BYTES>>>(
        p_latentH, INDIM, p_mWihH, INDIM, INDIM, mb, p_xg, G4);

    // launch 3: measure LSTM, persistent, 32 steps
    lstm_persist_k<HDIM, false, MEAS><<<dim3(64, 2), PTHREADS, measSmem>>>(
        nullptr, p_mWhhH, p_xg, p_h0, p_h1, p_lat, (long long)MEAS * HDIM);

    // launch 4: beat latent projection latproj = lat @ bWih[:, :H]^T + bb
    gemm_k<<<dim3(G4 / BNC, (BATCH * MEAS) / BM), 256, GSMEM_BYTES>>>(
        p_lat, HDIM, p_latWH, HDIM, HDIM, bb, p_latproj, G4);

    // launch 5: re-zero h0 + barriers
    zero_h_k<<<(BATCH * HDIM) / 256, 256>>>();

    // launch 6: beat LSTM, persistent, 512 steps
    lstm_persist_k<KBEAT, true, TBEAT><<<dim3(64, 2), PTHREADS, beatSmem>>>(
        p_inH, p_WbH, p_latproj, p_h0, p_h1, p_hall, (long long)TBEAT * HDIM);

    // launch 7: output head out = tanh(h_all) @ linW^T + linb
    gemm_k<<<dim3(ODIM / BNC, (BATCH * TBEAT) / BM), 256, GSMEM_BYTES>>>(
        p_hall, HDIM, p_linWH, HDIM, HDIM, linb, out, ODIM);
}

// round 13
// speedup vs baseline: 1.4502x; 1.1145x over previous
#include <cuda_runtime.h>
#include <cuda_fp16.h>
#include <math.h>
#include <stdint.h>

#define BATCH 256
#define MEAS  32
#define TBEAT 512
#define INDIM 512
#define HDIM  1024
#define ODIM  128
#define G4    4096
#define KBEAT 1152

#define BM    128
#define AP    72            // A stage pitch (halfs): 144B rows, ldmatrix conflict-free
#define PBK   64            // persistent-kernel K tile
#define PTHREADS 384        // 8 compute warps + 4 loader warps

// ---------------- scratch ----------------------------------------------------
__device__ __half g_WbH[G4 * KBEAT];    // beat weights, K order [inputs | h]
__device__ __half g_mWihH[G4 * INDIM];
__device__ __half g_mWhhH[G4 * HDIM];
__device__ __half g_latWH[G4 * HDIM];
__device__ __half g_linWH[ODIM * HDIM];
__device__ __half g_latentH[BATCH * MEAS * INDIM];
__device__ __half g_inH[BATCH * TBEAT * ODIM];
__device__ float  g_xg[BATCH * MEAS * G4];
__device__ __half g_lat[BATCH * MEAS * HDIM];
__device__ float  g_latproj[BATCH * MEAS * G4];
__device__ __half g_h0[BATCH * HDIM];
__device__ __half g_h1[BATCH * HDIM];
__device__ __half g_hall[BATCH * TBEAT * HDIM];
__device__ unsigned g_barG[64];         // [0] and [32]: per-row-group barriers

// MUFU tanh; sigmoid via tanh identity (abs err ~2^-11, masked by fp16 rounding)
__device__ __forceinline__ float tanh_fast(float x) {
    float r;
    asm("tanh.approx.f32 %0, %1;" : "=f"(r) : "f"(x));
    return r;
}
__device__ __forceinline__ float sig_fast(float x) {
    return fmaf(tanh_fast(0.5f * x), 0.5f, 0.5f);
}

__device__ __forceinline__ uint32_t s2u(const void* p) {
    uint32_t a;
    asm("{ .reg .u64 t; cvta.to.shared.u64 t, %1; cvt.u32.u64 %0, t; }"
        : "=r"(a) : "l"(p));
    return a;
}

__device__ __forceinline__ void mma_f16(float* c, const uint32_t* a, const uint32_t* b) {
    asm volatile(
        "mma.sync.aligned.m16n8k16.row.col.f32.f16.f16.f32 "
        "{%0,%1,%2,%3}, {%4,%5,%6,%7}, {%8,%9}, {%0,%1,%2,%3};"
        : "+f"(c[0]), "+f"(c[1]), "+f"(c[2]), "+f"(c[3])
        : "r"(a[0]), "r"(a[1]), "r"(a[2]), "r"(a[3]), "r"(b[0]), "r"(b[1]));
}

__device__ __forceinline__ void ldsm4(uint32_t& r0, uint32_t& r1, uint32_t& r2,
                                      uint32_t& r3, uint32_t saddr) {
    asm volatile("ldmatrix.sync.aligned.m8n8.x4.shared.b16 {%0,%1,%2,%3}, [%4];"
                 : "=r"(r0), "=r"(r1), "=r"(r2), "=r"(r3) : "r"(saddr));
}

__device__ __forceinline__ void cpa16(uint32_t sa, const void* g) {
    asm volatile("cp.async.cg.shared.global [%0], [%1], 16;" :: "r"(sa), "l"(g));
}
#define CPA_COMMIT() asm volatile("cp.async.commit_group;")
#define CPA_WAIT(n)  asm volatile("cp.async.wait_group %0;" :: "n"(n))

// ---------------- fused prep kernel ------------------------------------------
__global__ void prep_all_k(const float* __restrict__ latent,
                           const float* __restrict__ inputs,
                           const float* __restrict__ mWih,
                           const float* __restrict__ mWhh,
                           const float* __restrict__ bWih,
                           const float* __restrict__ bWhh,
                           const float* __restrict__ linW) {
    const int n = blockIdx.x;
    const int tid = threadIdx.x;
    for (int k = tid; k < INDIM; k += 256)
        g_mWihH[(size_t)n * INDIM + k] = __float2half(mWih[(size_t)n * INDIM + k]);
    for (int k = tid; k < HDIM; k += 256) {
        g_mWhhH[(size_t)n * HDIM + k] = __float2half(mWhh[(size_t)n * HDIM + k]);
        g_latWH[(size_t)n * HDIM + k] = __float2half(bWih[(size_t)n * KBEAT + k]);
    }
    // beat weights, K order [inputs(128) | h(1024)]
    for (int k = tid; k < KBEAT; k += 256) {
        float v = (k < ODIM) ? bWih[(size_t)n * KBEAT + HDIM + k]
                             : bWhh[(size_t)n * HDIM + (k - ODIM)];
        g_WbH[(size_t)n * KBEAT + k] = __float2half(v);
    }
    if (n < ODIM)
        for (int k = tid; k < HDIM; k += 256)
            g_linWH[(size_t)n * HDIM + k] = __float2half(linW[(size_t)n * HDIM + k]);
    {
        const size_t base = (size_t)n * 1024;
        for (int i = tid; i < 1024; i += 256)
            g_latentH[base + i] = __float2half(latent[base + i]);
    }
    {
        const size_t base = (size_t)n * 4096;
        for (int i = tid; i < 4096; i += 256)
            g_inH[base + i] = __float2half(inputs[base + i]);
    }
    if (tid < 64) g_h0[n * 64 + tid] = __float2half(0.f);
    if (n == 0 && tid < 64) g_barG[tid] = 0u;
}

__global__ void zero_h_k() {
    int i = blockIdx.x * blockDim.x + threadIdx.x;
    if (i < BATCH * HDIM) g_h0[i] = __float2half(0.f);
    if (i < 64) g_barG[i] = 0u;
}

// ---------------- persistent fused LSTM recurrence ---------------------------
// Grid 64x2 = 128 CTAs, 384 threads. W tile SMEM-resident; A streamed (4 slots,
// 3 in flight) by 4 DEDICATED loader warps (8-11); warps 0-7 compute m32 x n32
// tiles with fragment double-buffering; c-state + adds in registers; split
// 64-CTA release/acquire barrier between steps; MUFU fast activations.
template<int KDIM, bool HAS_EXTRA, int NSTEPS>
__global__ void __launch_bounds__(PTHREADS, 1) lstm_persist_k(
    const __half* __restrict__ extra,
    const __half* __restrict__ W,
    const float* __restrict__ add_base,
    __half* __restrict__ hb0, __half* __restrict__ hb1,
    __half* __restrict__ tanh_out, long long tanh_rstride)
{
    constexpr int WP = KDIM + 8;
    constexpr int nk = KDIM / PBK;
    extern __shared__ __half sm[];
    const uint32_t asmb = s2u(sm);                       // 4 * BM * AP halfs
    const uint32_t wsmb = asmb + 4 * BM * AP * 2;        // resident W

    const int tid  = threadIdx.x;
    const int wid  = tid >> 5;
    const int lane = tid & 31;
    const bool isLoader = (wid >= 8);
    const int wm   = (wid >> 1) & 3;    // compute warps: 32-row group
    const int wn   = wid & 1;           // compute warps: 8-unit group
    const int q    = lane & 3;
    const int rg   = lane >> 2;
    const int nblk = blockIdx.x;
    const int mblk = blockIdx.y * BM;
    unsigned* barp = &g_barG[blockIdx.y * 32];

    // ---- one-time: resident W tile load (gate-major smem rows) ----
    for (int idx = tid; idx < 64 * (KDIM / 8); idx += PTHREADS) {
        int sr = idx / (KDIM / 8);
        int k8 = (idx % (KDIM / 8)) * 8;
        int brow = ((sr >> 3) & 3) * HDIM + nblk * 16 + ((sr >> 5) << 3) + (sr & 7);
        cpa16(wsmb + (uint32_t)(sr * WP + k8) * 2, W + (size_t)brow * KDIM + k8);
    }
    CPA_COMMIT();
    CPA_WAIT(0);
    __syncthreads();

    // ---- loader mapping (warps 8-11): 8 chunks of 16B per thread per tile ----
    const int lt  = isLoader ? (tid - 256) : 0;   // 0..127
    const int rL  = lt >> 3;                       // 0..15
    const int k8L = (lt & 7) << 3;                 // 0..56
    uint32_t adst[8];
    const __half* exr[8];
#pragma unroll
    for (int i = 0; i < 8; i++) {
        adst[i] = (uint32_t)((rL + 16 * i) * AP + k8L) * 2;
        exr[i] = HAS_EXTRA ?
            (extra + (size_t)(mblk + rL + 16 * i) * (TBEAT * ODIM) + k8L)
            : (const __half*)0;
    }

    // ---- ldmatrix offsets (compute warps) ----
    const uint32_t aoff = (uint32_t)((wm * 32 + (lane & 15)) * AP + ((lane >> 4) << 3)) * 2;
    const uint32_t bbase = wsmb +
        (uint32_t)((wn * 32 + (lane & 7) + ((lane >> 4) << 3)) * WP + (((lane >> 3) & 1) << 3)) * 2;

    float creg[8];
#pragma unroll
    for (int i = 0; i < 8; i++) creg[i] = 0.f;
    unsigned barTarget = 0;

#pragma unroll 1
    for (int t = 0; t < NSTEPS; ++t) {
        const __half* hin = (t & 1) ? hb1 : hb0;
        __half* hout = (t & 1) ? hb0 : hb1;
        const int tOD = t * ODIM;

        auto issue = [&](int it) {       // loader threads only
            const int kt = it * PBK;
            const uint32_t sb = asmb + (uint32_t)(it & 3) * (BM * AP * 2);
#pragma unroll
            for (int i = 0; i < 8; i++) {
                const __half* src = (HAS_EXTRA && kt < ODIM)
                    ? (exr[i] + tOD + kt)
                    : (hin + (size_t)(mblk + rL + 16 * i) * HDIM + k8L
                       + (HAS_EXTRA ? (kt - ODIM) : kt));
                cpa16(sb + adst[i], src);
            }
            CPA_COMMIT();
        };

        // ---- pre-barrier: loaders issue barrier-independent input chunks;
        //      compute warps prefetch adds (L2-hot latproj/xg) ----
        if (isLoader) {
            if (HAS_EXTRA) { issue(0); issue(1); }
        }
        float2 ads[2][2][4];
        if (!isLoader) {
            const float* adp = add_base
                + (size_t)(HAS_EXTRA ? (t >> 4) : t) * G4;
            const int jb = nblk * 16 + wn * 8 + 2 * q;
#pragma unroll
            for (int mt = 0; mt < 2; mt++)
#pragma unroll
                for (int rs = 0; rs < 2; rs++) {
                    const int r = mblk + wm * 32 + mt * 16 + rg + rs * 8;
                    const float* ad = adp + (size_t)r * (MEAS * G4) + jb;
#pragma unroll
                    for (int gg = 0; gg < 4; gg++)
                        ads[mt][rs][gg] = *(const float2*)(ad + gg * HDIM);
                }
        }

        // ---- split-group barrier wait (h(t-1) visibility) ----
        if (t > 0) {
            if (tid == 0) {
                unsigned v;
                do {
                    asm volatile("ld.acquire.gpu.global.u32 %0, [%1];"
                                 : "=r"(v) : "l"(barp));
                } while (v < barTarget);
            }
            __syncthreads();
        }

        // ---- post-barrier: loaders issue h chunks; 3 groups in flight ----
        if (isLoader) {
            if (HAS_EXTRA) { issue(2); }
            else           { issue(0); issue(1); issue(2); }
        }

        float acc[2][4][4];
#pragma unroll
        for (int a = 0; a < 2; a++)
#pragma unroll
            for (int b = 0; b < 4; b++)
#pragma unroll
                for (int cc = 0; cc < 4; cc++) acc[a][b][cc] = 0.f;

#pragma unroll 1
        for (int it = 0; it < nk; ++it) {
            CPA_WAIT(2);                 // loaders: throttle; compute: no-op
            __syncthreads();
            if (!isLoader) {
                const uint32_t ab = asmb + (uint32_t)(it & 3) * (BM * AP * 2);
                const uint32_t kgb = (uint32_t)(it * PBK) * 2;

                uint32_t af[2][2][4], bf[2][4][2];
                auto ldfrag = [&](int buf, int ko) {
#pragma unroll
                    for (int mt = 0; mt < 2; mt++)
                        ldsm4(af[buf][mt][0], af[buf][mt][1], af[buf][mt][2], af[buf][mt][3],
                              ab + aoff + (uint32_t)(mt * 16 * AP + ko * 16) * 2);
#pragma unroll
                    for (int gp = 0; gp < 2; gp++)
                        ldsm4(bf[buf][gp * 2][0], bf[buf][gp * 2][1],
                              bf[buf][gp * 2 + 1][0], bf[buf][gp * 2 + 1][1],
                              bbase + (uint32_t)(gp * 16 * WP) * 2 + kgb + (uint32_t)(ko * 16) * 2);
                };

                ldfrag(0, 0);
#pragma unroll
                for (int ko = 0; ko < 4; ++ko) {
                    if (ko < 3) ldfrag((ko + 1) & 1, ko + 1);
                    const int cb = ko & 1;
#pragma unroll
                    for (int nt = 0; nt < 4; nt++)
#pragma unroll
                        for (int mt = 0; mt < 2; mt++)
                            mma_f16(acc[mt][nt], af[cb][mt], bf[cb][nt]);
                }
            } else {
                if (it + 3 < nk) issue(it + 3);
            }
        }
        CPA_WAIT(0);

        // ---- fused LSTM epilogue (MUFU activations; packed half2 stores) ----
        if (!isLoader) {
            const int jb = nblk * 16 + wn * 8 + 2 * q;
#pragma unroll
            for (int mt = 0; mt < 2; mt++)
#pragma unroll
                for (int rs = 0; rs < 2; rs++) {
                    const int r = mblk + wm * 32 + mt * 16 + rg + rs * 8;
                    __half2 hv, tv;
#pragma unroll
                    for (int ps = 0; ps < 2; ps++) {
                        const int ai = rs * 2 + ps;
                        float gi = acc[mt][0][ai] + (ps ? ads[mt][rs][0].y : ads[mt][rs][0].x);
                        float gf = acc[mt][1][ai] + (ps ? ads[mt][rs][1].y : ads[mt][rs][1].x);
                        float gg = acc[mt][2][ai] + (ps ? ads[mt][rs][2].y : ads[mt][rs][2].x);
                        float go = acc[mt][3][ai] + (ps ? ads[mt][rs][3].y : ads[mt][rs][3].x);
                        const int ci = mt * 4 + rs * 2 + ps;
                        float cc = sig_fast(gf) * creg[ci] + sig_fast(gi) * tanh_fast(gg);
                        creg[ci] = cc;
                        float hh = sig_fast(go) * tanh_fast(cc);
                        if (ps == 0) { hv.x = __float2half(hh); tv.x = __float2half(tanh_fast(hh)); }
                        else         { hv.y = __float2half(hh); tv.y = __float2half(tanh_fast(hh)); }
                    }
                    *(__half2*)(hout + (size_t)r * HDIM + jb) = hv;
                    *(__half2*)(tanh_out + (size_t)r * tanh_rstride
                                + (size_t)t * HDIM + jb) = tv;
                }
        }

        // ---- release arrive (release-atomic after CTA barrier) ----
        if (t + 1 < NSTEPS) {
            __syncthreads();
            if (tid == 0) {
                unsigned x;
                asm volatile("atom.add.release.gpu.global.u32 %0, [%1], 1;"
                             : "=r"(x) : "l"(barp));
            }
            barTarget += 64;
        }
    }
}

// ---------------- fp16 tensor GEMM (non-recurrent projections) --------------
// CTA tile 128x128, 8 warps each m32 x n64 (single-buffered fragments; 4
// warps/SMSP hide LDS latency). 4-stage cp.async pipeline.
#define BK   32
#define GBNC 128
#define GAP  40
#define GBP  40
#define GSTAGE_HALFS (BM * GAP + GBNC * GBP)
#define GSMEM_BYTES  (4 * GSTAGE_HALFS * 2)

__global__ void __launch_bounds__(256, 2) gemm_k(
    const __half* __restrict__ A, int lda,
    const __half* __restrict__ W, int ldw, int K,
    const float* __restrict__ bias,
    float* __restrict__ C, int ldc)
{
    extern __shared__ __half sm[];
    const uint32_t smb = s2u(sm);
    const int tid  = threadIdx.x;
    const int wid  = tid >> 5;
    const int lane = tid & 31;
    const int wm   = wid >> 1;          // 0..3 : 32-row group
    const int wn   = wid & 1;           // 0..1 : 64-col group
    const int q    = lane & 3;
    const int rg   = lane >> 2;
    const int mblk = blockIdx.y * BM;
    const int nblk = blockIdx.x;

    const int rA0 = tid >> 2, rA1 = rA0 + 64;
    const int k8a = (tid & 3) << 3;
    const __half* Ap0 = A + (size_t)(mblk + rA0) * lda + k8a;
    const __half* Ap1 = A + (size_t)(mblk + rA1) * lda + k8a;
    const uint32_t adst0 = (uint32_t)(rA0 * GAP + k8a) * 2;
    const uint32_t adst1 = (uint32_t)(rA1 * GAP + k8a) * 2;
    const int sr  = tid >> 2;
    const int k8b = (tid & 3) << 3;
    const __half* Bp0 = W + (size_t)(nblk * GBNC + sr) * ldw + k8b;
    const __half* Bp1 = W + (size_t)(nblk * GBNC + sr + 64) * ldw + k8b;
    const uint32_t bdst0 = (uint32_t)(BM * GAP + sr * GBP + k8b) * 2;
    const uint32_t bdst1 = (uint32_t)(BM * GAP + (sr + 64) * GBP + k8b) * 2;

    const int nk = K / BK;
    auto issue = [&](int s, int it) {
        const int kt = it * BK;
        const uint32_t sb = smb + (uint32_t)s * (GSTAGE_HALFS * 2);
        cpa16(sb + adst0, Ap0 + kt);
        cpa16(sb + adst1, Ap1 + kt);
        cpa16(sb + bdst0, Bp0 + kt);
        cpa16(sb + bdst1, Bp1 + kt);
    };
    issue(0, 0); CPA_COMMIT();
    issue(1, 1); CPA_COMMIT();
    issue(2, 2); CPA_COMMIT();

    const uint32_t aoff = (uint32_t)((wm * 32 + (lane & 15)) * GAP + ((lane >> 4) << 3)) * 2;
    const uint32_t boff = (uint32_t)(BM * GAP +
        (wn * 64 + (lane & 7) + ((lane >> 4) << 3)) * GBP + (((lane >> 3) & 1) << 3)) * 2;

    float acc[2][8][4];
#pragma unroll
    for (int a = 0; a < 2; a++)
#pragma unroll
        for (int b = 0; b < 8; b++)
#pragma unroll
            for (int cc = 0; cc < 4; cc++) acc[a][b][cc] = 0.f;

    int st = 0;
    for (int it = 0; it < nk; ++it) {
        CPA_WAIT(2);
        __syncthreads();
        const uint32_t sb = smb + (uint32_t)st * (GSTAGE_HALFS * 2);
#pragma unroll
        for (int ko = 0; ko < 2; ++ko) {
            uint32_t a[2][4];
#pragma unroll
            for (int mt = 0; mt < 2; mt++)
                ldsm4(a[mt][0], a[mt][1], a[mt][2], a[mt][3],
                      sb + aoff + (uint32_t)(mt * 16 * GAP + ko * 16) * 2);
            uint32_t bfr[8][2];
#pragma unroll
            for (int gp = 0; gp < 4; gp++)
                ldsm4(bfr[gp * 2][0], bfr[gp * 2][1],
                      bfr[gp * 2 + 1][0], bfr[gp * 2 + 1][1],
                      sb + boff + (uint32_t)(gp * 16 * GBP + ko * 16) * 2);
#pragma unroll
            for (int nt = 0; nt < 8; nt++)
#pragma unroll
                for (int mt = 0; mt < 2; mt++)
                    mma_f16(acc[mt][nt], a[mt], bfr[nt]);
        }
        if (it + 3 < nk) issue((it + 3) & 3, it + 3);
        CPA_COMMIT();
        st = (st + 1) & 3;
    }
    CPA_WAIT(0);

#pragma unroll
    for (int mt = 0; mt < 2; mt++)
#pragma unroll
        for (int nt = 0; nt < 8; nt++)
#pragma unroll
            for (int rs = 0; rs < 2; rs++) {
                const int r = mblk + wm * 32 + mt * 16 + rg + rs * 8;
                const int col = nblk * GBNC + wn * 64 + nt * 8 + 2 * q;
                float2 o;
                o.x = acc[mt][nt][rs * 2 + 0] + bias[col];
                o.y = acc[mt][nt][rs * 2 + 1] + bias[col + 1];
                *(float2*)&C[(size_t)r * ldc + col] = o;
            }
}

// ---------------------------------------------------------------------------
extern "C" void kernel_launch(void* const* d_in, const int* in_sizes, int n_in,
                              void* d_out, int out_size) {
    const float* latent = (const float*)d_in[0];
    const float* inputs = (const float*)d_in[1];
    const float* mWih   = (const float*)d_in[2];
    const float* mWhh   = (const float*)d_in[3];
    const float* mb     = (const float*)d_in[4];
    const float* bWih   = (const float*)d_in[5];
    const float* bWhh   = (const float*)d_in[6];
    const float* bb     = (const float*)d_in[7];
    const float* linW   = (const float*)d_in[8];
    const float* linb   = (const float*)d_in[9];
    float* out = (float*)d_out;

    __half *p_WbH, *p_mWihH, *p_mWhhH, *p_latWH, *p_linWH, *p_latentH, *p_inH;
    __half *p_lat, *p_h0, *p_h1, *p_hall;
    float *p_xg, *p_latproj;
    cudaGetSymbolAddress((void**)&p_WbH, g_WbH);
    cudaGetSymbolAddress((void**)&p_mWihH, g_mWihH);
    cudaGetSymbolAddress((void**)&p_mWhhH, g_mWhhH);
    cudaGetSymbolAddress((void**)&p_latWH, g_latWH);
    cudaGetSymbolAddress((void**)&p_linWH, g_linWH);
    cudaGetSymbolAddress((void**)&p_latentH, g_latentH);
    cudaGetSymbolAddress((void**)&p_inH, g_inH);
    cudaGetSymbolAddress((void**)&p_xg, g_xg);
    cudaGetSymbolAddress((void**)&p_lat, g_lat);
    cudaGetSymbolAddress((void**)&p_latproj, g_latproj);
    cudaGetSymbolAddress((void**)&p_h0, g_h0);
    cudaGetSymbolAddress((void**)&p_h1, g_h1);
    cudaGetSymbolAddress((void**)&p_hall, g_hall);

    const int measSmem = (4 * BM * AP + 64 * (HDIM + 8)) * 2;    // 205,824
    const int beatSmem = (4 * BM * AP + 64 * (KBEAT + 8)) * 2;   // 222,208
    cudaFuncSetAttribute(lstm_persist_k<HDIM, false, MEAS>,
                         cudaFuncAttributeMaxDynamicSharedMemorySize, measSmem);
    cudaFuncSetAttribute(lstm_persist_k<KBEAT, true, TBEAT>,
                         cudaFuncAttributeMaxDynamicSharedMemorySize, beatSmem);
    cudaFuncSetAttribute(gemm_k, cudaFuncAttributeMaxDynamicSharedMemorySize,
                         GSMEM_BYTES);

    // launch 1: fused prep (also zeroes h0 + barriers)
    prep_all_k<<<G4, 256>>>(latent, inputs, mWih, mWhh, bWih, bWhh, linW);

    // launch 2: measure input projection xg = latent @ mWih^T + mb
    gemm_k<<<dim3(G4 / GBNC, (BATCH * MEAS) / BM), 256, GSMEM_BYTES>>>(
        p_latentH, INDIM, p_mWihH, INDIM, INDIM, mb, p_xg, G4);

    // launch 3: measure LSTM, persistent, 32 steps
    lstm_persist_k<HDIM, false, MEAS><<<dim3(64, 2), PTHREADS, measSmem>>>(
        nullptr, p_mWhhH, p_xg, p_h0, p_h1, p_lat, (long long)MEAS * HDIM);

    // launch 4: beat latent projection latproj = lat @ bWih[:, :H]^T + bb
    gemm_k<<<dim3(G4 / GBNC, (BATCH * MEAS) / BM), 256, GSMEM_BYTES>>>(
        p_lat, HDIM, p_latWH, HDIM, HDIM, bb, p_latproj, G4);

    // launch 5: re-zero h0 + barriers
    zero_h_k<<<(BATCH * HDIM) / 256, 256>>>();

    // launch 6: beat LSTM, persistent, 512 steps
    lstm_persist_k<KBEAT, true, TBEAT><<<dim3(64, 2), PTHREADS, beatSmem>>>(
        p_inH, p_WbH, p_latproj, p_h0, p_h1, p_hall, (long long)TBEAT * HDIM);

    // launch 7: output head out = tanh(h_all) @ linW^T + linb
    gemm_k<<<dim3(ODIM / GBNC, (BATCH * TBEAT) / BM), 256, GSMEM_BYTES>>>(
        p_hall, HDIM, p_linWH, HDIM, HDIM, linb, out, ODIM);
}